// round 3
// baseline (speedup 1.0000x reference)
#include <cuda_runtime.h>
#include <math.h>

#define BB 16
#define CC 256
#define HH 128
#define WW 128
#define HWp (HH*WW)          // 16384
#define HW4 (HWp/4)          // 4096

// Scratch (device globals — no allocations allowed)
__device__ float g_sf[BB*2*HWp];     // [B,2,H,W]  avg(ch0), max(ch1)
__device__ float g_samp[BB*2*HWp];   // [B,2,H,W]
__device__ float g_w2eff[2*16*9];    // [2,16,3,3] channel-group-averaged w2
__device__ float g_b2eff[2];

// ---------------------------------------------------------------------------
// Kernel 1: channel reduce (avg + max over C=256). HBM-bound: 268 MB read.
// ---------------------------------------------------------------------------
__global__ void k_reduce(const float* __restrict__ x) {
    int idx = blockIdx.x * blockDim.x + threadIdx.x;   // 0..65535
    int b  = idx >> 12;            // / 4096
    int p4 = idx & 4095;
    const float4* xp = reinterpret_cast<const float4*>(x) + (size_t)b * CC * HW4 + p4;

    float4 s = make_float4(0.f, 0.f, 0.f, 0.f);
    float4 m = make_float4(-1e30f, -1e30f, -1e30f, -1e30f);
    #pragma unroll 8
    for (int c = 0; c < CC; ++c) {
        float4 v = __ldg(xp + (size_t)c * HW4);
        s.x += v.x; s.y += v.y; s.z += v.z; s.w += v.w;
        m.x = fmaxf(m.x, v.x); m.y = fmaxf(m.y, v.y);
        m.z = fmaxf(m.z, v.z); m.w = fmaxf(m.w, v.w);
    }
    const float inv = 1.0f / (float)CC;
    s.x *= inv; s.y *= inv; s.z *= inv; s.w *= inv;

    float4* o = reinterpret_cast<float4*>(g_sf);
    o[(size_t)b * 2 * HW4 + p4]       = s;   // avg  -> channel 0
    o[(size_t)b * 2 * HW4 + HW4 + p4] = m;   // max  -> channel 1
}

// ---------------------------------------------------------------------------
// Kernel 2: average w2/b2 over the 49-channel groups (conv linear => exact).
// ---------------------------------------------------------------------------
__global__ void k_w2eff(const float* __restrict__ w2, const float* __restrict__ b2) {
    int i = threadIdx.x;
    if (i < 288) {
        int d = i / 144;          // 0 or 1 (x / y offset group)
        int k = i % 144;          // [16,3,3] inner index
        float s = 0.f;
        #pragma unroll 7
        for (int j = 0; j < 49; ++j) s += w2[(size_t)(d * 49 + j) * 144 + k];
        g_w2eff[i] = s * (1.0f / 49.0f);
    }
    if (i < 2) {
        float s = 0.f;
        #pragma unroll 7
        for (int j = 0; j < 49; ++j) s += b2[i * 49 + j];
        g_b2eff[i] = s * (1.0f / 49.0f);
    }
}

// ---------------------------------------------------------------------------
// Kernel 3 (FUSED): conv3x3(2->16)+BN+ReLU -> conv3x3(16->2,eff)+bias
//                   -> tanh*0.5 -> grid -> bilinear grid_sample of sf.
// One block = 16x16 output tile. h1 lives only in shared memory.
// ---------------------------------------------------------------------------
__global__ void k_fused(const float* __restrict__ w1,
                        const float* __restrict__ gamma, const float* __restrict__ beta,
                        const float* __restrict__ mean,  const float* __restrict__ var) {
    __shared__ float sf_s[2][20][20];        // sf tile, halo 2
    __shared__ float h1_s[16][18][18];       // h1 tile, halo 1
    __shared__ float ws1[288], ws2[288];
    __shared__ float sc[16], bi[16], b2s[2];

    int t  = threadIdx.x;
    int bx = blockIdx.x;
    int b    = bx >> 6;
    int tile = bx & 63;
    int ty = tile >> 3, tx = tile & 7;
    int gy0 = ty * 16 - 2, gx0 = tx * 16 - 2;

    for (int i = t; i < 288; i += 256) { ws1[i] = w1[i]; ws2[i] = g_w2eff[i]; }
    if (t < 16) {
        float s = gamma[t] * rsqrtf(var[t] + 1e-5f);
        sc[t] = s;
        bi[t] = beta[t] - mean[t] * s;
    }
    if (t < 2) b2s[t] = g_b2eff[t];

    const float* sfb = g_sf + (size_t)b * 2 * HWp;

    // Phase 0: stage sf tile (zero-padded)
    for (int i = t; i < 800; i += 256) {
        int ch = i / 400, p = i % 400;
        int sy = p / 20, sx = p % 20;
        int gy = gy0 + sy, gx = gx0 + sx;
        float v = 0.f;
        if (gy >= 0 && gy < HH && gx >= 0 && gx < WW)
            v = sfb[ch * HWp + gy * WW + gx];
        sf_s[ch][sy][sx] = v;
    }
    __syncthreads();

    // Phase 1: h1 = relu(bn(conv1(sf))) on the 18x18 halo tile (smem only).
    // h1 pixels outside the image must be forced to 0 (conv2 zero-padding).
    for (int i = t; i < 324; i += 256) {
        int hy = i / 18, hx = i % 18;
        int gy = gy0 + 1 + hy, gx = gx0 + 1 + hx;
        bool inimg = (gy >= 0 && gy < HH && gx >= 0 && gx < WW);
        float v[18];
        #pragma unroll
        for (int c = 0; c < 2; ++c)
            #pragma unroll
            for (int kh = 0; kh < 3; ++kh)
                #pragma unroll
                for (int kw = 0; kw < 3; ++kw)
                    v[c * 9 + kh * 3 + kw] = sf_s[c][hy + kh][hx + kw];
        #pragma unroll
        for (int oc = 0; oc < 16; ++oc) {
            float acc = 0.f;
            #pragma unroll
            for (int k = 0; k < 18; ++k) acc = fmaf(v[k], ws1[oc * 18 + k], acc);
            acc = fmaf(acc, sc[oc], bi[oc]);
            acc = fmaxf(acc, 0.f);
            h1_s[oc][hy][hx] = inimg ? acc : 0.f;
        }
    }
    __syncthreads();

    // Phase 2: conv2 (16->2 effective) from smem, then offsets + sampling.
    int ly = t >> 4, lx = t & 15;
    int y = ty * 16 + ly, x = tx * 16 + lx;

    float accx = b2s[0], accy = b2s[1];
    #pragma unroll
    for (int kh = 0; kh < 3; ++kh)
        #pragma unroll
        for (int kw = 0; kw < 3; ++kw) {
            int wo = kh * 3 + kw;
            #pragma unroll
            for (int oc = 0; oc < 16; ++oc) {
                float val = h1_s[oc][ly + kh][lx + kw];
                accx = fmaf(val, ws2[oc * 9 + wo],       accx);
                accy = fmaf(val, ws2[144 + oc * 9 + wo], accy);
            }
        }

    float txo = tanhf(accx) * 0.5f;
    float tyo = tanhf(accy) * 0.5f;
    float gxv = fmaf((float)x, 2.0f / 127.0f, -1.0f) + txo;
    float gyv = fmaf((float)y, 2.0f / 127.0f, -1.0f) + tyo;
    gxv = fminf(fmaxf(gxv, -1.f), 1.f);
    gyv = fminf(fmaxf(gyv, -1.f), 1.f);

    // unnormalize (align_corners=False)
    float ix = ((gxv + 1.0f) * (float)WW - 1.0f) * 0.5f;
    float iy = ((gyv + 1.0f) * (float)HH - 1.0f) * 0.5f;
    float x0f = floorf(ix), y0f = floorf(iy);
    int x0 = (int)x0f, y0 = (int)y0f;
    int x1 = x0 + 1,   y1 = y0 + 1;
    float wx1 = ix - x0f, wx0 = 1.0f - wx1;
    float wy1 = iy - y0f, wy0 = 1.0f - wy1;

    const float* s0 = sfb;          // ch0 (avg)
    const float* s1 = sfb + HWp;    // ch1 (max)

    float w00 = wx0 * wy0, w10 = wx1 * wy0, w01 = wx0 * wy1, w11 = wx1 * wy1;
    bool vx0 = (x0 >= 0) & (x0 < WW), vx1 = (x1 >= 0) & (x1 < WW);
    bool vy0 = (y0 >= 0) & (y0 < HH), vy1 = (y1 >= 0) & (y1 < HH);

    float o0 = 0.f, o1 = 0.f;
    if (vy0 & vx0) { int p = y0 * WW + x0; o0 = fmaf(s0[p], w00, o0); o1 = fmaf(s1[p], w00, o1); }
    if (vy0 & vx1) { int p = y0 * WW + x1; o0 = fmaf(s0[p], w10, o0); o1 = fmaf(s1[p], w10, o1); }
    if (vy1 & vx0) { int p = y1 * WW + x0; o0 = fmaf(s0[p], w01, o0); o1 = fmaf(s1[p], w01, o1); }
    if (vy1 & vx1) { int p = y1 * WW + x1; o0 = fmaf(s0[p], w11, o0); o1 = fmaf(s1[p], w11, o1); }

    int rem = y * WW + x;
    g_samp[(size_t)b * 2 * HWp + rem]       = o0;
    g_samp[(size_t)b * 2 * HWp + HWp + rem] = o1;
}

// ---------------------------------------------------------------------------
// Kernel 4: conv7x7 (2->1, pad 3) + sigmoid, smem-tiled. One block = 16x16.
// ---------------------------------------------------------------------------
__global__ void k_attn(const float* __restrict__ aw, float* __restrict__ out) {
    __shared__ float ss[2][22][22];          // halo 3
    __shared__ float ws[98];
    int t = threadIdx.x;
    if (t < 98) ws[t] = aw[t];

    int bx = blockIdx.x;
    int b    = bx >> 6;
    int tile = bx & 63;
    int ty = tile >> 3, tx = tile & 7;
    int gy0 = ty * 16 - 3, gx0 = tx * 16 - 3;

    const float* sb = g_samp + (size_t)b * 2 * HWp;
    for (int i = t; i < 968; i += 256) {
        int ch = i / 484, p = i % 484;
        int sy = p / 22, sx = p % 22;
        int gy = gy0 + sy, gx = gx0 + sx;
        float v = 0.f;
        if (gy >= 0 && gy < HH && gx >= 0 && gx < WW)
            v = sb[ch * HWp + gy * WW + gx];
        ss[ch][sy][sx] = v;
    }
    __syncthreads();

    int ly = t >> 4, lx = t & 15;
    float acc = 0.f;
    #pragma unroll
    for (int kh = 0; kh < 7; ++kh)
        #pragma unroll
        for (int kw = 0; kw < 7; ++kw) {
            acc = fmaf(ss[0][ly + kh][lx + kw], ws[kh * 7 + kw],      acc);
            acc = fmaf(ss[1][ly + kh][lx + kw], ws[49 + kh * 7 + kw], acc);
        }

    int y = ty * 16 + ly, x = tx * 16 + lx;
    out[(size_t)b * HWp + y * WW + x] = 1.0f / (1.0f + expf(-acc));
}

// ---------------------------------------------------------------------------
extern "C" void kernel_launch(void* const* d_in, const int* in_sizes, int n_in,
                              void* d_out, int out_size) {
    const float* x     = (const float*)d_in[0];
    const float* w1    = (const float*)d_in[1];
    const float* gamma = (const float*)d_in[2];
    const float* beta  = (const float*)d_in[3];
    const float* mean  = (const float*)d_in[4];
    const float* var   = (const float*)d_in[5];
    const float* w2    = (const float*)d_in[6];
    const float* b2    = (const float*)d_in[7];
    const float* aw    = (const float*)d_in[8];
    float* out = (float*)d_out;

    k_reduce<<<256, 256>>>(x);
    k_w2eff<<<1, 512>>>(w2, b2);
    k_fused<<<1024, 256>>>(w1, gamma, beta, mean, var);
    k_attn<<<1024, 256>>>(aw, out);
}

// round 4
// speedup vs baseline: 1.3769x; 1.3769x over previous
#include <cuda_runtime.h>
#include <math.h>

#define BB 16
#define CC 256
#define HH 128
#define WW 128
#define HWp (HH*WW)          // 16384
#define HW4 (HWp/4)          // 4096

// Scratch (device globals — no allocations allowed)
__device__ float g_sf[BB*2*HWp];     // [B,2,H,W]  avg(ch0), max(ch1)
__device__ float g_h1[BB*16*HWp];    // [B,16,H,W]
__device__ float g_samp[BB*2*HWp];   // [B,2,H,W]
__device__ float g_w2eff[2*16*9];    // [2,16,3,3] channel-group-averaged w2
__device__ float g_b2eff[2];

// ---------------------------------------------------------------------------
// Kernel 1: channel reduce (avg + max over C=256). HBM-bound: 268 MB read.
// ---------------------------------------------------------------------------
__global__ void k_reduce(const float* __restrict__ x) {
    int idx = blockIdx.x * blockDim.x + threadIdx.x;   // 0..65535
    int b  = idx >> 12;
    int p4 = idx & 4095;
    const float4* xp = reinterpret_cast<const float4*>(x) + (size_t)b * CC * HW4 + p4;

    float4 s = make_float4(0.f, 0.f, 0.f, 0.f);
    float4 m = make_float4(-1e30f, -1e30f, -1e30f, -1e30f);
    #pragma unroll 8
    for (int c = 0; c < CC; ++c) {
        float4 v = __ldg(xp + (size_t)c * HW4);
        s.x += v.x; s.y += v.y; s.z += v.z; s.w += v.w;
        m.x = fmaxf(m.x, v.x); m.y = fmaxf(m.y, v.y);
        m.z = fmaxf(m.z, v.z); m.w = fmaxf(m.w, v.w);
    }
    const float inv = 1.0f / (float)CC;
    s.x *= inv; s.y *= inv; s.z *= inv; s.w *= inv;

    float4* o = reinterpret_cast<float4*>(g_sf);
    o[(size_t)b * 2 * HW4 + p4]       = s;   // avg  -> channel 0
    o[(size_t)b * 2 * HW4 + HW4 + p4] = m;   // max  -> channel 1
}

// ---------------------------------------------------------------------------
// Kernel 2: average w2/b2 over the 49-channel groups (conv linear => exact).
// ---------------------------------------------------------------------------
__global__ void k_w2eff(const float* __restrict__ w2, const float* __restrict__ b2) {
    int i = threadIdx.x;
    if (i < 288) {
        int d = i / 144;
        int k = i % 144;
        float s = 0.f;
        #pragma unroll 7
        for (int j = 0; j < 49; ++j) s += w2[(size_t)(d * 49 + j) * 144 + k];
        g_w2eff[i] = s * (1.0f / 49.0f);
    }
    if (i < 2) {
        float s = 0.f;
        #pragma unroll 7
        for (int j = 0; j < 49; ++j) s += b2[i * 49 + j];
        g_b2eff[i] = s * (1.0f / 49.0f);
    }
}

// ---------------------------------------------------------------------------
// Kernel 3: conv3x3 (2->16) + BN(eval) + ReLU. 4 pixels/thread (float4).
// ---------------------------------------------------------------------------
__global__ void k_conv1(const float* __restrict__ w1,
                        const float* __restrict__ gamma, const float* __restrict__ beta,
                        const float* __restrict__ mean,  const float* __restrict__ var) {
    __shared__ float ws[288];
    __shared__ float sc[16], bi[16];
    int t = threadIdx.x;
    for (int i = t; i < 288; i += blockDim.x) ws[i] = w1[i];
    if (t < 16) {
        float s = gamma[t] * rsqrtf(var[t] + 1e-5f);
        sc[t] = s;
        bi[t] = beta[t] - mean[t] * s;
    }
    __syncthreads();

    int idx = blockIdx.x * blockDim.x + t;      // 0..65535
    int b   = idx >> 12;
    int p4  = idx & 4095;
    int y   = p4 >> 5;
    int x4  = (p4 & 31) * 4;

    const float* sfb = g_sf + (size_t)b * 2 * HWp;

    // Neighborhood: c[ch][dy][6] covering columns x4-1 .. x4+4
    float c[2][3][6];
    #pragma unroll
    for (int ch = 0; ch < 2; ++ch)
        #pragma unroll
        for (int dy = 0; dy < 3; ++dy) {
            int yy = y + dy - 1;
            if (yy >= 0 && yy < HH) {
                const float* base = sfb + ch * HWp + yy * WW + x4;
                float4 mv = *reinterpret_cast<const float4*>(base);
                c[ch][dy][0] = (x4 > 0)   ? base[-1] : 0.f;
                c[ch][dy][1] = mv.x; c[ch][dy][2] = mv.y;
                c[ch][dy][3] = mv.z; c[ch][dy][4] = mv.w;
                c[ch][dy][5] = (x4 < 124) ? base[4]  : 0.f;
            } else {
                #pragma unroll
                for (int k = 0; k < 6; ++k) c[ch][dy][k] = 0.f;
            }
        }

    float* hb = g_h1 + (size_t)b * 16 * HWp + y * WW + x4;
    for (int oc = 0; oc < 16; ++oc) {
        float a0 = 0.f, a1 = 0.f, a2 = 0.f, a3 = 0.f;
        #pragma unroll
        for (int ch = 0; ch < 2; ++ch)
            #pragma unroll
            for (int dy = 0; dy < 3; ++dy)
                #pragma unroll
                for (int kw = 0; kw < 3; ++kw) {
                    float w = ws[oc * 18 + ch * 9 + dy * 3 + kw];
                    a0 = fmaf(c[ch][dy][kw    ], w, a0);
                    a1 = fmaf(c[ch][dy][kw + 1], w, a1);
                    a2 = fmaf(c[ch][dy][kw + 2], w, a2);
                    a3 = fmaf(c[ch][dy][kw + 3], w, a3);
                }
        float s = sc[oc], bo = bi[oc];
        float4 o;
        o.x = fmaxf(fmaf(a0, s, bo), 0.f);
        o.y = fmaxf(fmaf(a1, s, bo), 0.f);
        o.z = fmaxf(fmaf(a2, s, bo), 0.f);
        o.w = fmaxf(fmaf(a3, s, bo), 0.f);
        *reinterpret_cast<float4*>(hb + oc * HWp) = o;
    }
}

// ---------------------------------------------------------------------------
// Kernel 4: conv3x3 (16->2, averaged weights) + bias, tanh*0.5, grid,
// bilinear grid_sample of sf. 4 pixels/thread.
// ---------------------------------------------------------------------------
__global__ void k_off_sample() {
    __shared__ float ws[288];
    __shared__ float b2s[2];
    int t = threadIdx.x;
    for (int i = t; i < 288; i += blockDim.x) ws[i] = g_w2eff[i];
    if (t < 2) b2s[t] = g_b2eff[t];
    __syncthreads();

    int idx = blockIdx.x * blockDim.x + t;      // 0..65535
    int b   = idx >> 12;
    int p4  = idx & 4095;
    int y   = p4 >> 5;
    int x4  = (p4 & 31) * 4;

    const float* hb = g_h1 + (size_t)b * 16 * HWp;
    float ax[4], ay[4];
    #pragma unroll
    for (int j = 0; j < 4; ++j) { ax[j] = b2s[0]; ay[j] = b2s[1]; }

    for (int ic = 0; ic < 16; ++ic) {
        #pragma unroll
        for (int dy = 0; dy < 3; ++dy) {
            int yy = y + dy - 1;
            if (yy < 0 || yy >= HH) continue;
            const float* base = hb + ic * HWp + yy * WW + x4;
            float4 mv = *reinterpret_cast<const float4*>(base);
            float cl[6];
            cl[0] = (x4 > 0)   ? base[-1] : 0.f;
            cl[1] = mv.x; cl[2] = mv.y; cl[3] = mv.z; cl[4] = mv.w;
            cl[5] = (x4 < 124) ? base[4]  : 0.f;
            #pragma unroll
            for (int kw = 0; kw < 3; ++kw) {
                float wx = ws[ic * 9 + dy * 3 + kw];
                float wy = ws[144 + ic * 9 + dy * 3 + kw];
                #pragma unroll
                for (int j = 0; j < 4; ++j) {
                    ax[j] = fmaf(cl[kw + j], wx, ax[j]);
                    ay[j] = fmaf(cl[kw + j], wy, ay[j]);
                }
            }
        }
    }

    const float* s0 = g_sf + (size_t)b * 2 * HWp;  // avg
    const float* s1 = s0 + HWp;                    // max
    float o0[4], o1[4];

    #pragma unroll
    for (int j = 0; j < 4; ++j) {
        int x = x4 + j;
        float txo = tanhf(ax[j]) * 0.5f;
        float tyo = tanhf(ay[j]) * 0.5f;
        float gxv = fmaf((float)x, 2.0f / 127.0f, -1.0f) + txo;
        float gyv = fmaf((float)y, 2.0f / 127.0f, -1.0f) + tyo;
        gxv = fminf(fmaxf(gxv, -1.f), 1.f);
        gyv = fminf(fmaxf(gyv, -1.f), 1.f);

        float ix = ((gxv + 1.0f) * (float)WW - 1.0f) * 0.5f;
        float iy = ((gyv + 1.0f) * (float)HH - 1.0f) * 0.5f;
        float x0f = floorf(ix), y0f = floorf(iy);
        int x0 = (int)x0f, y0 = (int)y0f;
        int x1 = x0 + 1,   y1 = y0 + 1;
        float wx1 = ix - x0f, wx0 = 1.0f - wx1;
        float wy1 = iy - y0f, wy0 = 1.0f - wy1;

        float w00 = wx0 * wy0, w10 = wx1 * wy0, w01 = wx0 * wy1, w11 = wx1 * wy1;
        bool vx0 = (x0 >= 0) & (x0 < WW), vx1 = (x1 >= 0) & (x1 < WW);
        bool vy0 = (y0 >= 0) & (y0 < HH), vy1 = (y1 >= 0) & (y1 < HH);

        float r0 = 0.f, r1 = 0.f;
        if (vy0 & vx0) { int p = y0 * WW + x0; r0 = fmaf(s0[p], w00, r0); r1 = fmaf(s1[p], w00, r1); }
        if (vy0 & vx1) { int p = y0 * WW + x1; r0 = fmaf(s0[p], w10, r0); r1 = fmaf(s1[p], w10, r1); }
        if (vy1 & vx0) { int p = y1 * WW + x0; r0 = fmaf(s0[p], w01, r0); r1 = fmaf(s1[p], w01, r1); }
        if (vy1 & vx1) { int p = y1 * WW + x1; r0 = fmaf(s0[p], w11, r0); r1 = fmaf(s1[p], w11, r1); }
        o0[j] = r0; o1[j] = r1;
    }

    float* sp = g_samp + (size_t)b * 2 * HWp + y * WW + x4;
    *reinterpret_cast<float4*>(sp)       = make_float4(o0[0], o0[1], o0[2], o0[3]);
    *reinterpret_cast<float4*>(sp + HWp) = make_float4(o1[0], o1[1], o1[2], o1[3]);
}

// ---------------------------------------------------------------------------
// Kernel 5: conv7x7 (2->1, pad 3) + sigmoid. 4 pixels/thread.
// ---------------------------------------------------------------------------
__global__ void k_attn(const float* __restrict__ aw, float* __restrict__ out) {
    __shared__ float ws[98];
    int t = threadIdx.x;
    if (t < 98) ws[t] = aw[t];
    __syncthreads();

    int idx = blockIdx.x * blockDim.x + t;      // 0..65535
    int b   = idx >> 12;
    int p4  = idx & 4095;
    int y   = p4 >> 5;
    int x4  = (p4 & 31) * 4;

    const float* sb = g_samp + (size_t)b * 2 * HWp;
    float acc[4] = {0.f, 0.f, 0.f, 0.f};

    #pragma unroll
    for (int ch = 0; ch < 2; ++ch)
        #pragma unroll
        for (int dy = 0; dy < 7; ++dy) {
            int yy = y + dy - 3;
            if (yy < 0 || yy >= HH) continue;
            const float* base = sb + ch * HWp + yy * WW + x4;
            float4 mv = *reinterpret_cast<const float4*>(base);
            float cl[10];
            if (x4 > 0) {
                float4 lv = *reinterpret_cast<const float4*>(base - 4);
                cl[0] = lv.y; cl[1] = lv.z; cl[2] = lv.w;
            } else {
                cl[0] = cl[1] = cl[2] = 0.f;
            }
            cl[3] = mv.x; cl[4] = mv.y; cl[5] = mv.z; cl[6] = mv.w;
            if (x4 < 124) {
                float4 rv = *reinterpret_cast<const float4*>(base + 4);
                cl[7] = rv.x; cl[8] = rv.y; cl[9] = rv.z;
            } else {
                cl[7] = cl[8] = cl[9] = 0.f;
            }
            #pragma unroll
            for (int kw = 0; kw < 7; ++kw) {
                float w = ws[ch * 49 + dy * 7 + kw];
                #pragma unroll
                for (int j = 0; j < 4; ++j)
                    acc[j] = fmaf(cl[kw + j], w, acc[j]);
            }
        }

    float4 o;
    o.x = 1.0f / (1.0f + expf(-acc[0]));
    o.y = 1.0f / (1.0f + expf(-acc[1]));
    o.z = 1.0f / (1.0f + expf(-acc[2]));
    o.w = 1.0f / (1.0f + expf(-acc[3]));
    *reinterpret_cast<float4*>(out + (size_t)b * HWp + y * WW + x4) = o;
}

// ---------------------------------------------------------------------------
extern "C" void kernel_launch(void* const* d_in, const int* in_sizes, int n_in,
                              void* d_out, int out_size) {
    const float* x     = (const float*)d_in[0];
    const float* w1    = (const float*)d_in[1];
    const float* gamma = (const float*)d_in[2];
    const float* beta  = (const float*)d_in[3];
    const float* mean  = (const float*)d_in[4];
    const float* var   = (const float*)d_in[5];
    const float* w2    = (const float*)d_in[6];
    const float* b2    = (const float*)d_in[7];
    const float* aw    = (const float*)d_in[8];
    float* out = (float*)d_out;

    k_reduce<<<256, 256>>>(x);
    k_w2eff<<<1, 512>>>(w2, b2);
    k_conv1<<<256, 256>>>(w1, gamma, beta, mean, var);
    k_off_sample<<<256, 256>>>();
    k_attn<<<256, 256>>>(aw, out);
}